// round 16
// baseline (speedup 1.0000x reference)
#include <cuda_runtime.h>

// GVCNN group pooling collapsed to out[n,c] = sum_v coef[n,gid[n,v]] * RPs[n,v,c].
//
// R11 champion, EXACT structure and launch config (one 64-thread block per
// sample, channel-split across 2 warps, batched 12xLDG.128 register tile,
// 27-SHFL transpose-reduce (partial y[v] -> lane v), ONE __syncthreads,
// redundant warp-parallel binning via match_any+popc, warp-independent
// register epilogue, launch_bounds(64,12) -> natural regs=78, 12 CTAs/SM).
//
// Single isolated delta vs R11: streaming cache policy (__ldcs on the
// read-once tile, __stcs on the write-once output) to stop L2 from
// allocating dead lines. R15 showed the policy helps but its 13-CTA bound
// hurt more; this keeps the champion codegen.

#define NV 12
#define EPSF 1e-6f

__global__ __launch_bounds__(64, 12) void gvcnn_kernel(
    const float4* __restrict__ RPs4,   // [N, 12, 64] float4
    const float4* __restrict__ w4p,    // [64] float4
    const float*  __restrict__ b,
    float4*       __restrict__ out4)   // [N, 64] float4
{
    const int lane = threadIdx.x & 31;
    const int half = threadIdx.x >> 5;           // warp 0: chunks 0..31, warp 1: 32..63
    const size_t n = blockIdx.x;
    const int u    = half * 32 + lane;           // owned float4 chunk

    __shared__ float s_y[2][NV];

    // ---- batched loads: 12 independent coalesced LDG.128.CS, nothing between ----
    const float4* base = RPs4 + n * (NV * 64) + u;
    float4 r[NV];
#pragma unroll
    for (int v = 0; v < NV; v++) r[v] = __ldcs(base + v * 64);

    const float4 wv = w4p[u];
    const float  bb = b[0];

    // ---- 12 dot partials over this warp's 128 channels ----
    float p[NV];
#pragma unroll
    for (int v = 0; v < NV; v++)
        p[v] = r[v].x * wv.x + r[v].y * wv.y + r[v].z * wv.z + r[v].w * wv.w;

    // ---- transpose-reduce: partial y[v] lands in lane v (27 SHFLs) ----
#pragma unroll
    for (int i = 0; i < NV; i++)
        p[i] += __shfl_xor_sync(0xffffffffu, p[i], 16);

    const bool b8 = (lane & 8) != 0;
    const bool b4 = (lane & 4) != 0;
    const bool b2 = (lane & 2) != 0;
    const bool b1 = (lane & 1) != 0;

    float q8[8];
#pragma unroll
    for (int i = 0; i < 8; i++) {
        const float hiv  = (i + 8 < NV) ? p[i + 8] : 0.f;
        const float send = b8 ? p[i] : hiv;
        const float recv = __shfl_xor_sync(0xffffffffu, send, 8);
        q8[i] = (b8 ? hiv : p[i]) + recv;
    }
    float q4[4];
#pragma unroll
    for (int i = 0; i < 4; i++) {
        const float send = b4 ? q8[i] : q8[i + 4];
        const float recv = __shfl_xor_sync(0xffffffffu, send, 4);
        q4[i] = (b4 ? q8[i + 4] : q8[i]) + recv;
    }
    float q2[2];
#pragma unroll
    for (int i = 0; i < 2; i++) {
        const float send = b2 ? q4[i] : q4[i + 2];
        const float recv = __shfl_xor_sync(0xffffffffu, send, 2);
        q2[i] = (b2 ? q4[i + 2] : q4[i]) + recv;
    }
    float yh;
    {
        const float send = b1 ? q2[0] : q2[1];
        const float recv = __shfl_xor_sync(0xffffffffu, send, 1);
        yh = (b1 ? q2[1] : q2[0]) + recv;
    }
    // lane v (v<12) holds this warp's channel-half partial of y[v].

    if (lane < NV) s_y[half][lane] = yh;
    __syncthreads();                             // the ONLY barrier

    // ---- warp-parallel binning, redundantly in both warps (lane v owns view v) ----
    const int vl = (lane < NV) ? lane : 0;
    const float y = s_y[0][vl] + s_y[1][vl];

    const float x  = fabsf(y + bb) + EPSF;
    const float s  = x / (1.0f + x);                 // == sigmoid(log(x))
    const int  gid = min((int)(s * 10.0f), 9) >> 1;  // 0..4

    const unsigned mask = __match_any_sync(0xffffffffu, gid) & 0xFFFu;
    const int      gszI = __popc(mask);
    const float    gszF = (float)(gszI | (gszI == 0));
    const float    val  = ceilf(s * gszF);

    float numer = 0.f;
#pragma unroll
    for (int uu = 0; uu < NV; uu++) {
        const float vu = __shfl_sync(0xffffffffu, val, uu);
        if ((mask >> uu) & 1u) numer += vu;
    }
    const float gs = numer / (gszF + EPSF);          // reference group_score

    // total = sum over bins of gs == sum over views of gs/gsize
    float t = (lane < NV) ? gs / gszF : 0.f;
#pragma unroll
    for (int off = 16; off > 0; off >>= 1)
        t += __shfl_xor_sync(0xffffffffu, t, off);

    const float coef = gs / (gszF + EPSF) * (1.0f / (t + EPSF));

    // ---- broadcast the 12 coefficients, then warp-independent epilogue ----
    float cf[NV];
#pragma unroll
    for (int v = 0; v < NV; v++)
        cf[v] = __shfl_sync(0xffffffffu, coef, v);

    float4 acc = make_float4(0.f, 0.f, 0.f, 0.f);
#pragma unroll
    for (int v = 0; v < NV; v++) {
        acc.x += cf[v] * r[v].x;  acc.y += cf[v] * r[v].y;
        acc.z += cf[v] * r[v].z;  acc.w += cf[v] * r[v].w;
    }
    __stcs(out4 + n * 64 + u, acc);
}

extern "C" void kernel_launch(void* const* d_in, const int* in_sizes, int n_in,
                              void* d_out, int out_size)
{
    const float4* RPs4 = (const float4*)d_in[0];   // [8192,12,256] f32
    const float4* w4p  = (const float4*)d_in[1];   // [256] f32
    const float*  b    = (const float*)d_in[2];    // [1] f32
    float4* out4       = (float4*)d_out;           // [8192,256] f32

    const int n = in_sizes[0] / (NV * 256);        // 8192
    gvcnn_kernel<<<n, 64>>>(RPs4, w4p, b, out4);
}